// round 1
// baseline (speedup 1.0000x reference)
#include <cuda_runtime.h>
#include <mma.h>
#include <math.h>
#include <type_traits>

using namespace nvcuda;

#define DIM 128
#define SHALF 8192
#define WINDOW 128
#define LDS_PAD 136   // padded smem leading dim (floats)

// Scratch (no cudaMalloc allowed): precomputed M = Wq*Wk^T/sqrt(D), W2 = Wv*Wo,
// and gelu(beta) for the all-zero second half.
__device__ float g_M[DIM * DIM];
__device__ float g_W2[DIM * DIM];
__device__ __align__(16) float g_gb[DIM];

__device__ __forceinline__ float gelu_erf(float y) {
    return 0.5f * y * (1.0f + erff(y * 0.70710678118654752440f));
}

// ---------------------------------------------------------------------------
// Prep: M[i][j] = sum_d Wq[i,d]*Wk[j,d] / sqrt(D); W2 = Wv @ Wo; g_gb = gelu(beta)
// grid 257 x 128 threads
// ---------------------------------------------------------------------------
__global__ void prep_kernel(const float* __restrict__ Wq,
                            const float* __restrict__ Wk,
                            const float* __restrict__ Wv,
                            const float* __restrict__ Wo,
                            const float* __restrict__ beta) {
    int bid = blockIdx.x;
    int j = threadIdx.x;
    __shared__ float arow[DIM];
    if (bid < 128) {
        int i = bid;
        arow[j] = Wq[i * DIM + j];
        __syncthreads();
        float s = 0.f;
#pragma unroll 8
        for (int d = 0; d < DIM; d++) s += arow[d] * Wk[j * DIM + d];
        g_M[i * DIM + j] = s * 0.08838834764831844055f;  // 1/sqrt(128)
    } else if (bid < 256) {
        int i = bid - 128;
        arow[j] = Wv[i * DIM + j];
        __syncthreads();
        float s = 0.f;
#pragma unroll 8
        for (int d = 0; d < DIM; d++) s += arow[d] * Wo[d * DIM + j];
        g_W2[i * DIM + j] = s;
    } else {
        g_gb[j] = gelu_erf(beta[j]);
    }
}

// ---------------------------------------------------------------------------
// 128x128x128 GEMM on smem tiles via wmma tf32 (m16n16k8).
// 8 warps: warp_m = wid&3 (32 rows), warp_n = wid>>2 (64 cols); 2x4 frag tiles.
// COLB: B operand read column-major (i.e., B = X^T when X stored row-major).
// ---------------------------------------------------------------------------
template <bool COLB>
__device__ __forceinline__ void gemm128(const float* __restrict__ A,
                                        const float* __restrict__ B,
                                        float* __restrict__ C, int wid) {
    using BL = typename std::conditional<COLB, wmma::col_major, wmma::row_major>::type;
    const int wm = wid & 3;
    const int wn = wid >> 2;

    wmma::fragment<wmma::accumulator, 16, 16, 8, float> acc[2][4];
#pragma unroll
    for (int i = 0; i < 2; i++)
#pragma unroll
        for (int j = 0; j < 4; j++) wmma::fill_fragment(acc[i][j], 0.0f);

#pragma unroll
    for (int k = 0; k < DIM; k += 8) {
        wmma::fragment<wmma::matrix_a, 16, 16, 8, wmma::precision::tf32, wmma::row_major> a[2];
        wmma::fragment<wmma::matrix_b, 16, 16, 8, wmma::precision::tf32, BL> b[4];
#pragma unroll
        for (int i = 0; i < 2; i++) {
            wmma::load_matrix_sync(a[i], A + (wm * 32 + i * 16) * LDS_PAD + k, LDS_PAD);
#pragma unroll
            for (int t = 0; t < a[i].num_elements; t++)
                a[i].x[t] = wmma::__float_to_tf32(a[i].x[t]);
        }
#pragma unroll
        for (int j = 0; j < 4; j++) {
            const float* bp = COLB ? (B + (wn * 64 + j * 16) * LDS_PAD + k)
                                   : (B + k * LDS_PAD + wn * 64 + j * 16);
            wmma::load_matrix_sync(b[j], bp, LDS_PAD);
#pragma unroll
            for (int t = 0; t < b[j].num_elements; t++)
                b[j].x[t] = wmma::__float_to_tf32(b[j].x[t]);
        }
#pragma unroll
        for (int i = 0; i < 2; i++)
#pragma unroll
            for (int j = 0; j < 4; j++) wmma::mma_sync(acc[i][j], a[i], b[j], acc[i][j]);
    }
#pragma unroll
    for (int i = 0; i < 2; i++)
#pragma unroll
        for (int j = 0; j < 4; j++)
            wmma::store_matrix_sync(C + (wm * 32 + i * 16) * LDS_PAD + wn * 64 + j * 16,
                                    acc[i][j], LDS_PAD, wmma::mem_row_major);
}

// ---------------------------------------------------------------------------
// Main: one CTA per (batch, block). P=X@M; S=P@X^T; softmax; T=A@X; H=T@W2;
// LayerNorm + exact GELU; write first-half output.
// ---------------------------------------------------------------------------
__global__ void __launch_bounds__(256, 1)
attn_kernel(const float* __restrict__ x, const float* __restrict__ gamma,
            const float* __restrict__ beta, float* __restrict__ out,
            int nblk_per_b) {
    extern __shared__ float sm[];
    float* Xs = sm;                       // X, later H
    float* BufA = sm + 128 * LDS_PAD;     // M -> scores/attn -> W2
    float* BufB = sm + 2 * 128 * LDS_PAD; // P -> T
    __shared__ float s_mu[128], s_rs[128], s_g[128], s_b[128];

    const int tid = threadIdx.x;
    const int wid = tid >> 5;
    const int cta = blockIdx.x;
    const int batch = cta / nblk_per_b;
    const int blk = cta - batch * nblk_per_b;

    const float* Xg = x + ((size_t)batch * SHALF + (size_t)blk * WINDOW) * DIM;

    if (tid < 128) { s_g[tid] = gamma[tid]; s_b[tid] = beta[tid]; }
    for (int idx = tid; idx < 128 * 128; idx += 256) {
        int r = idx >> 7, c = idx & 127;
        Xs[r * LDS_PAD + c] = Xg[idx];
        BufA[r * LDS_PAD + c] = g_M[idx];
    }
    __syncthreads();

    gemm128<false>(Xs, BufA, BufB, wid);   // P = X @ M
    __syncthreads();
    gemm128<true>(BufB, Xs, BufA, wid);    // S = P @ X^T  (scale already in M)
    __syncthreads();

    // row softmax on BufA (2 threads per row)
    {
        int row = tid >> 1, h = tid & 1;
        float* rp = BufA + row * LDS_PAD + h * 64;
        float m = -1e30f;
#pragma unroll 8
        for (int i = 0; i < 64; i++) m = fmaxf(m, rp[i]);
        m = fmaxf(m, __shfl_xor_sync(0xffffffffu, m, 1));
        float s = 0.f;
#pragma unroll 8
        for (int i = 0; i < 64; i++) { float e = __expf(rp[i] - m); rp[i] = e; s += e; }
        s += __shfl_xor_sync(0xffffffffu, s, 1);
        float inv = 1.0f / s;
#pragma unroll 8
        for (int i = 0; i < 64; i++) rp[i] *= inv;
    }
    __syncthreads();

    gemm128<false>(BufA, Xs, BufB, wid);   // T = attn @ X
    __syncthreads();

    for (int idx = tid; idx < 128 * 128; idx += 256) {
        int r = idx >> 7, c = idx & 127;
        BufA[r * LDS_PAD + c] = g_W2[idx];  // attn dead -> W2
    }
    __syncthreads();

    gemm128<false>(BufB, BufA, Xs, wid);   // H = T @ W2 -> Xs (X dead)
    __syncthreads();

    // LayerNorm stats (2 threads per row)
    {
        int row = tid >> 1, h = tid & 1;
        const float* hr = Xs + row * LDS_PAD + h * 64;
        float s = 0.f, s2 = 0.f;
#pragma unroll 8
        for (int i = 0; i < 64; i++) { float v = hr[i]; s += v; s2 += v * v; }
        s += __shfl_xor_sync(0xffffffffu, s, 1);
        s2 += __shfl_xor_sync(0xffffffffu, s2, 1);
        if (h == 0) {
            float mu = s * (1.0f / 128.0f);
            float var = s2 * (1.0f / 128.0f) - mu * mu;
            s_mu[row] = mu;
            s_rs[row] = rsqrtf(var + 1e-5f);
        }
    }
    __syncthreads();

    float* Og = out + ((size_t)batch * 2 * SHALF + (size_t)blk * WINDOW) * DIM;
    for (int idx = tid; idx < 128 * 128; idx += 256) {
        int r = idx >> 7, c = idx & 127;
        float y = (Xs[r * LDS_PAD + c] - s_mu[r]) * s_rs[r] * s_g[c] + s_b[c];
        Og[idx] = gelu_erf(y);
    }
}

// ---------------------------------------------------------------------------
// Second half of every batch is exactly gelu(beta) broadcast (zero-padded blocks).
// ---------------------------------------------------------------------------
__global__ void fill_second_half(float4* __restrict__ out4, int B) {
    const float4* gb4 = reinterpret_cast<const float4*>(g_gb);
    const int per_b = SHALF * DIM / 4;  // 262144 float4 per batch half
    int total = B * per_b;
    for (int i = blockIdx.x * blockDim.x + threadIdx.x; i < total;
         i += gridDim.x * blockDim.x) {
        int b = i / per_b;
        int rem = i - b * per_b;
        out4[(size_t)b * (2 * per_b) + per_b + rem] = gb4[rem & 31];
    }
}

extern "C" void kernel_launch(void* const* d_in, const int* in_sizes, int n_in,
                              void* d_out, int out_size) {
    const float* x     = (const float*)d_in[0];
    const float* Wq    = (const float*)d_in[1];
    const float* Wk    = (const float*)d_in[2];
    const float* Wv    = (const float*)d_in[3];
    const float* Wo    = (const float*)d_in[4];
    const float* gamma = (const float*)d_in[5];
    const float* beta  = (const float*)d_in[6];
    float* out = (float*)d_out;

    int B = in_sizes[0] / (SHALF * DIM);      // 8
    int nblk = SHALF / WINDOW;                // 64

    const int smem_bytes = 3 * 128 * LDS_PAD * (int)sizeof(float);  // 208896
    cudaFuncSetAttribute(attn_kernel, cudaFuncAttributeMaxDynamicSharedMemorySize,
                         smem_bytes);

    prep_kernel<<<257, 128>>>(Wq, Wk, Wv, Wo, beta);
    attn_kernel<<<B * nblk, 256, smem_bytes>>>(x, gamma, beta, out, nblk);
    fill_second_half<<<2048, 256>>>((float4*)d_out, B);
}

// round 4
// speedup vs baseline: 1.5937x; 1.5937x over previous
#include <cuda_runtime.h>
#include <cstdint>
#include <math.h>

#define DIM 128
#define SHALF 8192
#define NBLK 64
#define LD 132            // smem leading dim (floats): conflict-free for frag loads
#define BUF (128 * LD)    // one 128x128 padded tile

// ---------------------------------------------------------------------------
// Device scratch (no cudaMalloc allowed)
// g_Mt[n][k]  = sum_d Wk[n,d]*Wq[k,d]/sqrt(D)  (tf32-rounded)
// g_W2t[j][k] = sum_d Wv[k,d]*Wo[d,j]          (tf32-rounded)
// ---------------------------------------------------------------------------
__device__ float g_Mt[DIM * DIM];
__device__ float g_W2t[DIM * DIM];
__device__ __align__(16) float g_gb[DIM];

__device__ __forceinline__ uint32_t f2tf32(float f) {
    uint32_t r;
    asm("cvt.rna.tf32.f32 %0, %1;" : "=r"(r) : "f"(f));
    return r;
}

__device__ __forceinline__ float gelu_erf(float y) {
    return 0.5f * y * (1.0f + erff(y * 0.70710678118654752440f));
}

__device__ __forceinline__ void mma8(float acc[4], const uint32_t a[4], const uint32_t b[2]) {
    asm volatile(
        "mma.sync.aligned.m16n8k8.row.col.f32.tf32.tf32.f32 "
        "{%0,%1,%2,%3}, {%4,%5,%6,%7}, {%8,%9}, {%0,%1,%2,%3};"
        : "+f"(acc[0]), "+f"(acc[1]), "+f"(acc[2]), "+f"(acc[3])
        : "r"(a[0]), "r"(a[1]), "r"(a[2]), "r"(a[3]), "r"(b[0]), "r"(b[1]));
}

// ---------------------------------------------------------------------------
// 128x128x128 GEMM on smem tiles. 8 warps: wm=wid&3 (32 rows), wn=wid>>2
// (64 cols); per warp 2x8 m16n8k8 tiles per k-step.
// BCOL=false: B is row-major [n][k] (C = A @ B^T). BCOL=true: B is [k][n].
// RND: round C to tf32 at store (when C feeds a later mma as operand).
// C may alias A: a pre-store __syncthreads() separates k-loop reads from stores.
// ---------------------------------------------------------------------------
template <bool BCOL, bool RND>
__device__ __noinline__ void gemm_tile(int aOff, int bOff, int cOff) {
    extern __shared__ float smx[];
    const int tid = threadIdx.x;
    const int lane = tid & 31;
    const int wid = tid >> 5;
    const int g = lane >> 2, cc = lane & 3;
    const int wm = wid & 3, wn = wid >> 2;

    const float* A = smx + aOff + (wm * 32 + g) * LD + cc;
    const float* B = BCOL ? (smx + bOff + cc * LD + wn * 64 + g)
                          : (smx + bOff + (wn * 64 + g) * LD + cc);

    float acc[2][8][4];
#pragma unroll
    for (int mi = 0; mi < 2; mi++)
#pragma unroll
        for (int ni = 0; ni < 8; ni++)
#pragma unroll
            for (int e = 0; e < 4; e++) acc[mi][ni][e] = 0.f;

#pragma unroll 4
    for (int k = 0; k < 16; k++) {
        const int k8 = k * 8;
        uint32_t a[2][4];
#pragma unroll
        for (int mi = 0; mi < 2; mi++) {
            a[mi][0] = __float_as_uint(A[(mi * 16) * LD + k8]);
            a[mi][1] = __float_as_uint(A[(mi * 16 + 8) * LD + k8]);
            a[mi][2] = __float_as_uint(A[(mi * 16) * LD + k8 + 4]);
            a[mi][3] = __float_as_uint(A[(mi * 16 + 8) * LD + k8 + 4]);
        }
        uint32_t b[8][2];
#pragma unroll
        for (int ni = 0; ni < 8; ni++) {
            if (BCOL) {
                b[ni][0] = __float_as_uint(B[k8 * LD + 8 * ni]);
                b[ni][1] = __float_as_uint(B[(k8 + 4) * LD + 8 * ni]);
            } else {
                b[ni][0] = __float_as_uint(B[(8 * ni) * LD + k8]);
                b[ni][1] = __float_as_uint(B[(8 * ni) * LD + k8 + 4]);
            }
        }
#pragma unroll
        for (int mi = 0; mi < 2; mi++)
#pragma unroll
            for (int ni = 0; ni < 8; ni++) mma8(acc[mi][ni], a[mi], b[ni]);
    }

    __syncthreads();  // all warps done reading A/B before C store (C may alias A)

    float* C = smx + cOff + (wm * 32 + g) * LD + wn * 64 + 2 * cc;
#pragma unroll
    for (int mi = 0; mi < 2; mi++)
#pragma unroll
        for (int ni = 0; ni < 8; ni++) {
            float2 lo, hi;
            if (RND) {
                lo.x = __uint_as_float(f2tf32(acc[mi][ni][0]));
                lo.y = __uint_as_float(f2tf32(acc[mi][ni][1]));
                hi.x = __uint_as_float(f2tf32(acc[mi][ni][2]));
                hi.y = __uint_as_float(f2tf32(acc[mi][ni][3]));
            } else {
                lo.x = acc[mi][ni][0]; lo.y = acc[mi][ni][1];
                hi.x = acc[mi][ni][2]; hi.y = acc[mi][ni][3];
            }
            *(float2*)(C + (mi * 16) * LD + 8 * ni) = lo;
            *(float2*)(C + (mi * 16 + 8) * LD + 8 * ni) = hi;
        }
    __syncthreads();
}

// ---------------------------------------------------------------------------
// Prep: strip-parallel 128x128x128 GEMMs (fp32), outputs pre-rounded to tf32.
// bid 0-7 : Mt strips;  bid 8-15 : W2t strips;  bid 16 : gelu(beta)
// ---------------------------------------------------------------------------
__global__ void __launch_bounds__(256) prep_kernel(const float* __restrict__ Wq,
                                                   const float* __restrict__ Wk,
                                                   const float* __restrict__ Wv,
                                                   const float* __restrict__ Wo,
                                                   const float* __restrict__ beta) {
    int bid = blockIdx.x;
    int tid = threadIdx.x;
    if (bid == 16) {
        if (tid < DIM) g_gb[tid] = gelu_erf(beta[tid]);
        return;
    }
    extern __shared__ float ps[];
    float* As = ps;              // [128][129]
    float* Bs = ps + 128 * 129;  // [16][128]
    const bool modeM = bid < 8;
    const int strip = (bid & 7) * 16;

    if (modeM) {
        for (int i = tid; i < 16384; i += 256) As[(i >> 7) * 129 + (i & 127)] = Wk[i];
        for (int i = tid; i < 2048; i += 256)
            Bs[i] = Wq[(strip + (i >> 7)) * DIM + (i & 127)];
    } else {
        for (int i = tid; i < 16384; i += 256) As[(i & 127) * 129 + (i >> 7)] = Wo[i];
        for (int i = tid; i < 2048; i += 256)
            Bs[i] = Wv[(strip + (i >> 7)) * DIM + (i & 127)];
    }
    __syncthreads();

    const int r = tid >> 1, h = tid & 1;
    float acc[8] = {0.f, 0.f, 0.f, 0.f, 0.f, 0.f, 0.f, 0.f};
    const float* ar = As + r * 129;
#pragma unroll 4
    for (int k = 0; k < 128; k++) {
        float a = ar[k];
#pragma unroll
        for (int j = 0; j < 8; j++) acc[j] += a * Bs[(h * 8 + j) * DIM + k];
    }
    float* dst = (modeM ? g_Mt : g_W2t) + r * DIM + strip + h * 8;
    const float sc = modeM ? 0.08838834764831844055f : 1.0f;
#pragma unroll
    for (int j = 0; j < 8; j++) dst[j] = __uint_as_float(f2tf32(acc[j] * sc));
}

// ---------------------------------------------------------------------------
// Main: one CTA per (batch, block), 256 threads, 8 warps.
// Buffers: Xs [0], Wb [BUF] (Mt -> W2t), Scratch [2*BUF] (P -> S -> attn -> T -> H)
// ---------------------------------------------------------------------------
__global__ void __launch_bounds__(256, 1)
attn_kernel(const float* __restrict__ x, const float* __restrict__ gamma,
            const float* __restrict__ beta, float* __restrict__ out) {
    extern __shared__ float smx[];
    __shared__ float s_mu[128], s_rs[128], s_g[DIM], s_b[DIM];

    const int tid = threadIdx.x;
    const int batch = blockIdx.x >> 6;
    const int blk = blockIdx.x & 63;

    if (tid < DIM) { s_g[tid] = gamma[tid]; s_b[tid] = beta[tid]; }

    // Load X (rounded to tf32) and Mt
    const float4* Xg4 = (const float4*)(x + ((size_t)batch * SHALF + (size_t)blk * 128) * DIM);
    const float4* M4 = (const float4*)g_Mt;
    for (int i = tid; i < 4096; i += 256) {
        int r = i >> 5, c4 = (i & 31) << 2;
        float4 v = Xg4[i];
        float4 t;
        t.x = __uint_as_float(f2tf32(v.x));
        t.y = __uint_as_float(f2tf32(v.y));
        t.z = __uint_as_float(f2tf32(v.z));
        t.w = __uint_as_float(f2tf32(v.w));
        *(float4*)(smx + r * LD + c4) = t;
        *(float4*)(smx + BUF + r * LD + c4) = M4[i];
    }
    __syncthreads();

    gemm_tile<false, true>(0, BUF, 2 * BUF);          // P = X @ Mt^T

    // Mt dead -> load W2t into Wb (barrier inside gemm guarantees G1 reads done;
    // next Wb reader is G4, separated by multiple barriers)
    {
        const float4* W4 = (const float4*)g_W2t;
        for (int i = tid; i < 4096; i += 256) {
            int r = i >> 5, c4 = (i & 31) << 2;
            *(float4*)(smx + BUF + r * LD + c4) = W4[i];
        }
    }

    gemm_tile<false, false>(2 * BUF, 0, 2 * BUF);     // S = P @ X^T  (in place)

    // Softmax: 2 threads per row, 64 cols each, exchange via shfl.
    {
        const int row = tid >> 1, h = tid & 1;
        float* rp = smx + 2 * BUF + row * LD + h * 64;
        float4 v[16];
#pragma unroll
        for (int i = 0; i < 16; i++) v[i] = *(float4*)(rp + 4 * i);
        float m = -1e30f;
#pragma unroll
        for (int i = 0; i < 16; i++)
            m = fmaxf(m, fmaxf(fmaxf(v[i].x, v[i].y), fmaxf(v[i].z, v[i].w)));
        m = fmaxf(m, __shfl_xor_sync(0xffffffffu, m, 1));
        float s = 0.f;
#pragma unroll
        for (int i = 0; i < 16; i++) {
            v[i].x = __expf(v[i].x - m); v[i].y = __expf(v[i].y - m);
            v[i].z = __expf(v[i].z - m); v[i].w = __expf(v[i].w - m);
            s += v[i].x + v[i].y + v[i].z + v[i].w;
        }
        s += __shfl_xor_sync(0xffffffffu, s, 1);
        float inv = 1.0f / s;
#pragma unroll
        for (int i = 0; i < 16; i++) {
            v[i].x = __uint_as_float(f2tf32(v[i].x * inv));
            v[i].y = __uint_as_float(f2tf32(v[i].y * inv));
            v[i].z = __uint_as_float(f2tf32(v[i].z * inv));
            v[i].w = __uint_as_float(f2tf32(v[i].w * inv));
            *(float4*)(rp + 4 * i) = v[i];
        }
    }
    __syncthreads();

    gemm_tile<true, true>(2 * BUF, 0, 2 * BUF);       // T = attn @ X
    gemm_tile<false, false>(2 * BUF, BUF, 2 * BUF);   // H = T @ W2t^T

    // LayerNorm stats: 2 threads per row
    {
        const int row = tid >> 1, h = tid & 1;
        const float* hr = smx + 2 * BUF + row * LD + h * 64;
        float s1 = 0.f, s2 = 0.f;
#pragma unroll
        for (int i = 0; i < 64; i += 4) {
            float4 v = *(const float4*)(hr + i);
            s1 += v.x + v.y + v.z + v.w;
            s2 += v.x * v.x + v.y * v.y + v.z * v.z + v.w * v.w;
        }
        s1 += __shfl_xor_sync(0xffffffffu, s1, 1);
        s2 += __shfl_xor_sync(0xffffffffu, s2, 1);
        if (h == 0) {
            float mu = s1 * (1.0f / 128.0f);
            float var = s2 * (1.0f / 128.0f) - mu * mu;
            s_mu[row] = mu;
            s_rs[row] = rsqrtf(var + 1e-5f);
        }
    }
    __syncthreads();

    // Epilogue: LN + exact GELU, coalesced float4 writes
    float4* Og4 = (float4*)(out + ((size_t)batch * 2 * SHALF + (size_t)blk * 128) * DIM);
    for (int i = tid; i < 4096; i += 256) {
        int r = i >> 5, c4 = (i & 31) << 2;
        float mu = s_mu[r], rs = s_rs[r];
        const float* hp = smx + 2 * BUF + r * LD + c4;
        float4 o;
        o.x = gelu_erf((hp[0] - mu) * rs * s_g[c4 + 0] + s_b[c4 + 0]);
        o.y = gelu_erf((hp[1] - mu) * rs * s_g[c4 + 1] + s_b[c4 + 1]);
        o.z = gelu_erf((hp[2] - mu) * rs * s_g[c4 + 2] + s_b[c4 + 2]);
        o.w = gelu_erf((hp[3] - mu) * rs * s_g[c4 + 3] + s_b[c4 + 3]);
        Og4[i] = o;
    }
}

// ---------------------------------------------------------------------------
// Second half of every batch is gelu(beta) broadcast (zero-padded blocks).
// ---------------------------------------------------------------------------
__global__ void fill_second_half(float4* __restrict__ out4, int B) {
    const float4* gb4 = reinterpret_cast<const float4*>(g_gb);
    const int per_b = SHALF * DIM / 4;
    int total = B * per_b;
    for (int i = blockIdx.x * blockDim.x + threadIdx.x; i < total;
         i += gridDim.x * blockDim.x) {
        int b = i / per_b;
        int rem = i - b * per_b;
        out4[(size_t)b * (2 * per_b) + per_b + rem] = gb4[rem & 31];
    }
}

extern "C" void kernel_launch(void* const* d_in, const int* in_sizes, int n_in,
                              void* d_out, int out_size) {
    const float* x     = (const float*)d_in[0];
    const float* Wq    = (const float*)d_in[1];
    const float* Wk    = (const float*)d_in[2];
    const float* Wv    = (const float*)d_in[3];
    const float* Wo    = (const float*)d_in[4];
    const float* gamma = (const float*)d_in[5];
    const float* beta  = (const float*)d_in[6];
    float* out = (float*)d_out;

    int B = in_sizes[0] / (SHALF * DIM);  // 8

    const int prep_smem = (128 * 129 + 16 * 128) * (int)sizeof(float);  // 74240
    const int attn_smem = 3 * BUF * (int)sizeof(float);                 // 202752
    cudaFuncSetAttribute(prep_kernel, cudaFuncAttributeMaxDynamicSharedMemorySize, prep_smem);
    cudaFuncSetAttribute(attn_kernel, cudaFuncAttributeMaxDynamicSharedMemorySize, attn_smem);

    prep_kernel<<<17, 256, prep_smem>>>(Wq, Wk, Wv, Wo, beta);
    attn_kernel<<<B * NBLK, 256, attn_smem>>>(x, gamma, beta, out);
    fill_second_half<<<2048, 256>>>((float4*)d_out, B);
}